// round 5
// baseline (speedup 1.0000x reference)
#include <cuda_runtime.h>
#include <cstdint>

#define HEADS 4
#define CB    8192
#define D     64
#define M     8192            // B*N
#define DIM   256             // HEADS*D
#define QSIZE (M*DIM)         // floats of quantize output
#define TM 64                 // queries per block
#define TN 128                // codes per tile
#define NTILES (CB/TN)        // 64
#define XROW 66               // u64 per Xdup row (64 + 2 pad -> 528B, bank-group stagger)

// smem layout (dynamic): Xdup[64*66] u64 | Et[64*128] f32 | y2s[128] | inds[64]
#define SM_XDUP_BYTES (TM*XROW*8)           // 33792
#define SM_ET_OFF     SM_XDUP_BYTES
#define SM_ET_BYTES   (D*TN*4)              // 32768
#define SM_Y2_OFF     (SM_ET_OFF + SM_ET_BYTES)
#define SM_INDS_OFF   (SM_Y2_OFF + TN*4)
#define SMEM_BYTES    (SM_INDS_OFF + TM*4)  // 67328

__device__ float g_y2[HEADS*CB];

// ---------------------------------------------------------------------------
// y2[h*CB+c] = |embed[h][c]|^2   (one warp per code)
// ---------------------------------------------------------------------------
__global__ void vq_y2_kernel(const float* __restrict__ embed) {
    int gw   = (blockIdx.x * blockDim.x + threadIdx.x) >> 5;
    int lane = threadIdx.x & 31;
    if (gw >= HEADS * CB) return;
    float2 v = reinterpret_cast<const float2*>(embed + (size_t)gw * D)[lane];
    float s = fmaf(v.x, v.x, v.y * v.y);
    #pragma unroll
    for (int o = 16; o; o >>= 1) s += __shfl_xor_sync(0xffffffffu, s, o);
    if (lane == 0) g_y2[gw] = s;
}

// packed f32x2 FMA — full-rate fp32 path (ptxas never emits from C++)
__device__ __forceinline__ void ffma2(unsigned long long& acc,
                                      unsigned long long a,
                                      unsigned long long b) {
    asm("fma.rn.f32x2 %0, %1, %2, %0;" : "+l"(acc) : "l"(a), "l"(b));
}

__device__ __forceinline__ unsigned long long dup2(float v) {
    unsigned u = __float_as_uint(v);
    return ((unsigned long long)u << 32) | u;
}

__device__ __forceinline__ void upd(float sc, int cg, float& m, int& id) {
    if (sc > m) { m = sc; id = cg; }
}

// ---------------------------------------------------------------------------
// Fused distance GEMM + argmax + gather.
// grid = (M/TM, HEADS), block 256 (tx=t&15 -> code groups, ty=t>>4 -> query rows)
// Frag: 4 queries x 8 codes, acc packs 2 adjacent codes per f32x2.
// score(c) = x.e_c - 0.5*|e_c|^2
// ---------------------------------------------------------------------------
__global__ __launch_bounds__(256, 3)
void vq_main_kernel(const float* __restrict__ x, const float* __restrict__ embed,
                    float* __restrict__ out, int out_size) {
    extern __shared__ char smem[];
    unsigned long long* Xd = reinterpret_cast<unsigned long long*>(smem);
    float* Et   = reinterpret_cast<float*>(smem + SM_ET_OFF);   // [k][c] k-major
    float* y2s  = reinterpret_cast<float*>(smem + SM_Y2_OFF);
    int*   inds = reinterpret_cast<int*>(smem + SM_INDS_OFF);

    const int h  = blockIdx.y;
    const int m0 = blockIdx.x * TM;
    const int t  = threadIdx.x;
    const int tx = t & 15;
    const int ty = t >> 4;

    // ---- X fill: duplicated (x,x) u64 per k, row stride 66 u64 ----
    #pragma unroll
    for (int s = 0; s < 4; s++) {
        int slot = t + s * 256;
        int r = slot >> 4, kq = slot & 15;
        float4 f = *reinterpret_cast<const float4*>(
            x + (size_t)(m0 + r) * DIM + h * D + kq * 4);
        unsigned long long* p = Xd + r * XROW + kq * 4;
        p[0] = dup2(f.x); p[1] = dup2(f.y); p[2] = dup2(f.z); p[3] = dup2(f.w);
    }

    float rmax[4];
    int   ridx[4];
    #pragma unroll
    for (int i = 0; i < 4; i++) { rmax[i] = -3.4e38f; ridx[i] = 0; }

    const float* ebase = embed + (size_t)h * CB * D;
    const float* y2b   = g_y2 + h * CB;

    for (int tile = 0; tile < NTILES; tile++) {
        const int n0 = tile * TN;
        __syncthreads();                     // prior reads of Et/y2s done (and X fill on iter 0)
        // ---- E fill, transposed to k-major: Et[k*128 + c] = e[c][k] ----
        // lane->c mapping keeps the 4 STS.32 per float4 conflict-free.
        #pragma unroll
        for (int s = 0; s < 8; s++) {
            int slot = t + s * 256;
            int c = slot & 127, kq = slot >> 7;
            float4 f = *reinterpret_cast<const float4*>(
                ebase + (size_t)(n0 + c) * D + kq * 4);
            Et[(4 * kq + 0) * TN + c] = f.x;
            Et[(4 * kq + 1) * TN + c] = f.y;
            Et[(4 * kq + 2) * TN + c] = f.z;
            Et[(4 * kq + 3) * TN + c] = f.w;
        }
        if (t < TN) y2s[t] = y2b[n0 + t];
        __syncthreads();

        // ---- 4x8 frag, acc packs code pairs: acc[i][jp] = (dot c_even, dot c_odd) ----
        unsigned long long acc[4][4];
        #pragma unroll
        for (int i = 0; i < 4; i++)
            #pragma unroll
            for (int jp = 0; jp < 4; jp++) acc[i][jp] = 0ull;

        const float4* EtF = reinterpret_cast<const float4*>(Et);
        #pragma unroll 8
        for (int k2 = 0; k2 < 32; k2++) {           // 2 k per step
            // E: rows 2k2, 2k2+1; cols [4tx..4tx+3] and [64+4tx..64+4tx+3]
            float4 a0 = EtF[(2 * k2) * 32 + tx];
            float4 b0 = EtF[(2 * k2) * 32 + tx + 16];
            float4 a1 = EtF[(2 * k2 + 1) * 32 + tx];
            float4 b1 = EtF[(2 * k2 + 1) * 32 + tx + 16];
            ulonglong2 eA0 = *reinterpret_cast<ulonglong2*>(&a0);
            ulonglong2 eB0 = *reinterpret_cast<ulonglong2*>(&b0);
            ulonglong2 eA1 = *reinterpret_cast<ulonglong2*>(&a1);
            ulonglong2 eB1 = *reinterpret_cast<ulonglong2*>(&b1);
            #pragma unroll
            for (int i = 0; i < 4; i++) {
                // (dup x_k, dup x_{k+1}) for this query row
                ulonglong2 xv = *reinterpret_cast<const ulonglong2*>(
                    Xd + (4 * ty + i) * XROW + 2 * k2);
                ffma2(acc[i][0], xv.x, eA0.x);
                ffma2(acc[i][1], xv.x, eA0.y);
                ffma2(acc[i][2], xv.x, eB0.x);
                ffma2(acc[i][3], xv.x, eB0.y);
                ffma2(acc[i][0], xv.y, eA1.x);
                ffma2(acc[i][1], xv.y, eA1.y);
                ffma2(acc[i][2], xv.y, eB1.x);
                ffma2(acc[i][3], xv.y, eB1.y);
            }
        }

        // ---- epilogue: running argmax, ascending code order (first-index ties) ----
        float4 yA = reinterpret_cast<const float4*>(y2s)[tx];
        float4 yB = reinterpret_cast<const float4*>(y2s)[tx + 16];
        const int cA = n0 + 4 * tx;        // codes cA..cA+3
        const int cB = n0 + 64 + 4 * tx;   // codes cB..cB+3
        #pragma unroll
        for (int i = 0; i < 4; i++) {
            unsigned long long a;
            a = acc[i][0];
            upd(__uint_as_float((unsigned)a)        - 0.5f * yA.x, cA + 0, rmax[i], ridx[i]);
            upd(__uint_as_float((unsigned)(a >> 32)) - 0.5f * yA.y, cA + 1, rmax[i], ridx[i]);
            a = acc[i][1];
            upd(__uint_as_float((unsigned)a)        - 0.5f * yA.z, cA + 2, rmax[i], ridx[i]);
            upd(__uint_as_float((unsigned)(a >> 32)) - 0.5f * yA.w, cA + 3, rmax[i], ridx[i]);
            a = acc[i][2];
            upd(__uint_as_float((unsigned)a)        - 0.5f * yB.x, cB + 0, rmax[i], ridx[i]);
            upd(__uint_as_float((unsigned)(a >> 32)) - 0.5f * yB.y, cB + 1, rmax[i], ridx[i]);
            a = acc[i][3];
            upd(__uint_as_float((unsigned)a)        - 0.5f * yB.z, cB + 2, rmax[i], ridx[i]);
            upd(__uint_as_float((unsigned)(a >> 32)) - 0.5f * yB.w, cB + 3, rmax[i], ridx[i]);
        }
    }

    // ---- reduce over the 16 tx lanes (offsets <=8 stay within the half-warp) ----
    #pragma unroll
    for (int i = 0; i < 4; i++) {
        float v = rmax[i];
        int  id = ridx[i];
        #pragma unroll
        for (int o = 8; o; o >>= 1) {
            float ov = __shfl_xor_sync(0xffffffffu, v, o);
            int   oi = __shfl_xor_sync(0xffffffffu, id, o);
            if (ov > v || (ov == v && oi < id)) { v = ov; id = oi; }
        }
        if (tx == 0) inds[4 * ty + i] = id;
    }
    __syncthreads();

    // ---- indices output (as float, layout b n h) ----
    if (out_size >= QSIZE + M * HEADS && t < TM)
        out[QSIZE + (size_t)(m0 + t) * HEADS + h] = (float)inds[t];

    // ---- gather quantized codes (layout b n (h d)) ----
    #pragma unroll
    for (int s = 0; s < 4; s++) {
        int slot = t + s * 256;
        int r = slot >> 4, kq = slot & 15;
        int id = inds[r];
        float4 v = *reinterpret_cast<const float4*>(ebase + (size_t)id * D + kq * 4);
        *reinterpret_cast<float4*>(out + (size_t)(m0 + r) * DIM + h * D + kq * 4) = v;
    }
}

extern "C" void kernel_launch(void* const* d_in, const int* in_sizes, int n_in,
                              void* d_out, int out_size) {
    const float* x     = (const float*)d_in[0];   // [4,2048,256]
    const float* embed = (const float*)d_in[1];   // [4,8192,64]
    float* out = (float*)d_out;

    cudaFuncSetAttribute(vq_main_kernel,
                         cudaFuncAttributeMaxDynamicSharedMemorySize, SMEM_BYTES);

    vq_y2_kernel<<<(HEADS * CB) / 8, 256>>>(embed);

    dim3 grid(M / TM, HEADS);
    vq_main_kernel<<<grid, 256, SMEM_BYTES>>>(x, embed, out, out_size);
}